// round 8
// baseline (speedup 1.0000x reference)
#include <cuda_runtime.h>
#include <cuda_bf16.h>
#include <math.h>
#include <stdint.h>

// ---------------- constants ----------------
#define Bc   8
#define Sc   256
#define Dc   512
#define Hc   8
#define DKc  256
#define HDc  2048
#define DFFc 2048
#define Lc   4
#define NQKV 6144

#define BSD  (Bc*Sc*Dc)
#define BSHD (Bc*Sc*HDc)
#define BSF  (Bc*Sc*DFFc)
#define WSZ  (Dc*HDc)

// ---------------- scratch ----------------
__device__ __align__(16) float g_x   [BSD];
__device__ __align__(16) float g_part[4*BSD];
__device__ __align__(16) float g_bqkv[Lc*NQKV];
__device__ __align__(16) __nv_bfloat16 g_x2b [BSD];
__device__ __align__(16) __nv_bfloat16 g_qkvb[Bc*Sc*NQKV];
__device__ __align__(16) __nv_bfloat16 g_ob  [BSHD];
__device__ __align__(16) __nv_bfloat16 g_fb  [BSF];
__device__ __align__(16) __nv_bfloat16 g_wqkv[Lc*Dc*NQKV];
__device__ __align__(16) __nv_bfloat16 g_wo  [Lc*WSZ];
__device__ __align__(16) __nv_bfloat16 g_w1  [Lc*WSZ];
__device__ __align__(16) __nv_bfloat16 g_w2  [Lc*WSZ];

// ---------------- async copy / mma helpers ----------------
__device__ __forceinline__ void cpa16(void* s, const void* g) {
    uint32_t sa = (uint32_t)__cvta_generic_to_shared(s);
    asm volatile("cp.async.cg.shared.global [%0], [%1], 16;" :: "r"(sa), "l"(g) : "memory");
}
__device__ __forceinline__ void cpa_commit() {
    asm volatile("cp.async.commit_group;" ::: "memory");
}
__device__ __forceinline__ void cpa_wait0() {
    asm volatile("cp.async.wait_group 0;" ::: "memory");
}
__device__ __forceinline__ void cpa_wait2() {
    asm volatile("cp.async.wait_group 2;" ::: "memory");
}
__device__ __forceinline__ void ldsm4(uint32_t& r0, uint32_t& r1, uint32_t& r2, uint32_t& r3, uint32_t a) {
    asm volatile("ldmatrix.sync.aligned.m8n8.x4.shared.b16 {%0,%1,%2,%3}, [%4];"
                 : "=r"(r0), "=r"(r1), "=r"(r2), "=r"(r3) : "r"(a));
}
__device__ __forceinline__ void ldsm4t(uint32_t& r0, uint32_t& r1, uint32_t& r2, uint32_t& r3, uint32_t a) {
    asm volatile("ldmatrix.sync.aligned.m8n8.x4.trans.shared.b16 {%0,%1,%2,%3}, [%4];"
                 : "=r"(r0), "=r"(r1), "=r"(r2), "=r"(r3) : "r"(a));
}
#define MMA_BF16(acc, a0,a1,a2,a3, b0,b1) \
    asm volatile("mma.sync.aligned.m16n8k16.row.col.f32.bf16.bf16.f32 " \
                 "{%0,%1,%2,%3}, {%4,%5,%6,%7}, {%8,%9}, {%0,%1,%2,%3};" \
                 : "+f"(acc[0]), "+f"(acc[1]), "+f"(acc[2]), "+f"(acc[3]) \
                 : "r"(a0), "r"(a1), "r"(a2), "r"(a3), "r"(b0), "r"(b1))

// ---------------- weight conversion ----------------
__global__ void f2b_qkv_kernel(const float* __restrict__ Wq,
                               const float* __restrict__ Wk,
                               const float* __restrict__ Wv,
                               __nv_bfloat16* __restrict__ dst)
{
    int i = blockIdx.x * blockDim.x + threadIdx.x;
    int total4 = Lc * Dc * NQKV / 4;
    if (i >= total4) return;
    int col = (i % (NQKV / 4)) * 4;
    int row = (i / (NQKV / 4)) % Dc;
    int layer = i / (NQKV / 4 * Dc);
    int sel = col >> 11, c = col & 2047;
    const float* src = (sel == 0 ? Wq : sel == 1 ? Wk : Wv)
                       + (size_t)layer * WSZ + (size_t)row * HDc + c;
    float4 v = *(const float4*)src;
    __nv_bfloat162 lo, hi;
    lo.x = __float2bfloat16_rn(v.x); lo.y = __float2bfloat16_rn(v.y);
    hi.x = __float2bfloat16_rn(v.z); hi.y = __float2bfloat16_rn(v.w);
    __nv_bfloat162* d2 = (__nv_bfloat162*)(dst + ((size_t)layer * Dc + row) * NQKV + col);
    d2[0] = lo; d2[1] = hi;
}

__global__ void f2b_multi_kernel(const float* __restrict__ s0, __nv_bfloat16* __restrict__ d0,
                                 const float* __restrict__ s1, __nv_bfloat16* __restrict__ d1,
                                 const float* __restrict__ s2, __nv_bfloat16* __restrict__ d2,
                                 int n4)
{
    int i = blockIdx.x * blockDim.x + threadIdx.x;
    if (i >= 3 * n4) return;
    int seg = i / n4, j = i - seg * n4;
    const float* s = (seg == 0 ? s0 : seg == 1 ? s1 : s2);
    __nv_bfloat16* d = (seg == 0 ? d0 : seg == 1 ? d1 : d2);
    float4 v = ((const float4*)s)[j];
    __nv_bfloat162 lo, hi;
    lo.x = __float2bfloat16_rn(v.x); lo.y = __float2bfloat16_rn(v.y);
    hi.x = __float2bfloat16_rn(v.z); hi.y = __float2bfloat16_rn(v.w);
    ((__nv_bfloat162*)d)[2*j]   = lo;
    ((__nv_bfloat162*)d)[2*j+1] = hi;
}

__global__ void bias_qkv_kernel(const float* __restrict__ bq,
                                const float* __restrict__ bk,
                                const float* __restrict__ bv,
                                float* __restrict__ dst)
{
    int i = blockIdx.x * blockDim.x + threadIdx.x;
    if (i >= Lc * NQKV) return;
    int col = i % NQKV, layer = i / NQKV;
    int sel = col >> 11, c = col & 2047;
    const float* s = (sel == 0 ? bq : sel == 1 ? bk : bv);
    dst[i] = s[layer * HDc + c];
}

// ---------------- LN helpers ----------------
__device__ __forceinline__ float2 ln_stats(float4 v, int t, float* sh)
{
    float s = v.x + v.y + v.z + v.w;
    #pragma unroll
    for (int o = 16; o; o >>= 1) s += __shfl_xor_sync(0xFFFFFFFFu, s, o);
    if ((t & 31) == 0) sh[t >> 5] = s;
    __syncthreads();
    float mean = (sh[0] + sh[1] + sh[2] + sh[3]) * (1.0f / (float)Dc);
    float dx = v.x - mean, dy = v.y - mean, dz = v.z - mean, dw = v.w - mean;
    float q = dx*dx + dy*dy + dz*dz + dw*dw;
    __syncthreads();
    #pragma unroll
    for (int o = 16; o; o >>= 1) q += __shfl_xor_sync(0xFFFFFFFFu, q, o);
    if ((t & 31) == 0) sh[t >> 5] = q;
    __syncthreads();
    float var = (sh[0] + sh[1] + sh[2] + sh[3]) * (1.0f / (float)(Dc - 1));
    float inv = 1.0f / (sqrtf(var) + 1e-6f);
    return make_float2(mean, inv);
}

// fused embed + LN: x = data*sqrt(D)+pe+seg ; x2b = LN(x)
__global__ void embed_ln_kernel(const float* __restrict__ data,
                                const float* __restrict__ seg,
                                const int*   __restrict__ view_idx,
                                const float* __restrict__ alpha,
                                const float* __restrict__ beta,
                                float* __restrict__ x,
                                __nv_bfloat16* __restrict__ y)
{
    int row = blockIdx.x, t = threadIdx.x;
    __shared__ float sh[4];
    int s = row & (Sc - 1);
    int seg_row = view_idx[0] * Sc;
    size_t off = (size_t)row * Dc + t * 4;
    float4 dv = *(const float4*)(data + off);
    float4 v;
    #pragma unroll
    for (int j = 0; j < 4; j++) {
        int d = t * 4 + j;
        float angle = (float)s * exp2f(-(float)d * (1.0f / 32.0f));
        float pe = (d & 1) ? cosf(angle) : sinf(angle);
        float dd = (j == 0 ? dv.x : j == 1 ? dv.y : j == 2 ? dv.z : dv.w);
        float e = dd * 22.62741699796952f + pe + seg[seg_row * Dc + d];
        (j == 0 ? v.x : j == 1 ? v.y : j == 2 ? v.z : v.w) = e;
    }
    *(float4*)(x + off) = v;
    float2 mi = ln_stats(v, t, sh);
    float4 a = ((const float4*)alpha)[t];
    float4 b = ((const float4*)beta)[t];
    __nv_bfloat162 o0, o1;
    o0.x = __float2bfloat16_rn(a.x * (v.x - mi.x) * mi.y + b.x);
    o0.y = __float2bfloat16_rn(a.y * (v.y - mi.x) * mi.y + b.y);
    o1.x = __float2bfloat16_rn(a.z * (v.z - mi.x) * mi.y + b.z);
    o1.y = __float2bfloat16_rn(a.w * (v.w - mi.x) * mi.y + b.w);
    __nv_bfloat162* yr = (__nv_bfloat162*)(y + (size_t)row * Dc);
    yr[2*t] = o0; yr[2*t+1] = o1;
}

__global__ void reduce_ln_kernel(const float* __restrict__ part,
                                 const float* __restrict__ bias,
                                 float* __restrict__ x,
                                 const float* __restrict__ alpha,
                                 const float* __restrict__ beta,
                                 __nv_bfloat16* __restrict__ ybf,
                                 float* __restrict__ yf)
{
    int row = blockIdx.x, t = threadIdx.x;
    __shared__ float sh[4];
    size_t off = (size_t)row * Dc + t * 4;
    float4 v = *(const float4*)(x + off);
    #pragma unroll
    for (int s = 0; s < 4; s++) {
        float4 p = *(const float4*)(part + (size_t)s * BSD + off);
        v.x += p.x; v.y += p.y; v.z += p.z; v.w += p.w;
    }
    float4 b4 = ((const float4*)bias)[t];
    v.x += b4.x; v.y += b4.y; v.z += b4.z; v.w += b4.w;
    *(float4*)(x + off) = v;

    float2 mi = ln_stats(v, t, sh);
    float4 a = ((const float4*)alpha)[t];
    float4 bb = ((const float4*)beta)[t];
    float y0 = a.x * (v.x - mi.x) * mi.y + bb.x;
    float y1 = a.y * (v.y - mi.x) * mi.y + bb.y;
    float y2 = a.z * (v.z - mi.x) * mi.y + bb.z;
    float y3 = a.w * (v.w - mi.x) * mi.y + bb.w;
    if (ybf) {
        __nv_bfloat162 o0, o1;
        o0.x = __float2bfloat16_rn(y0); o0.y = __float2bfloat16_rn(y1);
        o1.x = __float2bfloat16_rn(y2); o1.y = __float2bfloat16_rn(y3);
        __nv_bfloat162* yr = (__nv_bfloat162*)(ybf + (size_t)row * Dc);
        yr[2*t] = o0; yr[2*t+1] = o1;
    } else {
        *(float4*)(yf + off) = make_float4(y0, y1, y2, y3);
    }
}

// ---------------- fused attention (unchanged from R6) ----------------
#define PQA 264
#define PKA 264
#define ATT_SMEM ((128*PQA + 256*PKA) * 2 + 512*4 + 256*4)

__global__ __launch_bounds__(512, 1)
void attn_kernel(const __nv_bfloat16* __restrict__ qkv,
                 const int* __restrict__ attn_m,
                 __nv_bfloat16* __restrict__ out)
{
    extern __shared__ __nv_bfloat16 smh[];
    __nv_bfloat16* sQ = smh;
    __nv_bfloat16* sK = smh + 128 * PQA;
    float* red  = (float*)(smh + 128 * PQA + 256 * PKA);
    int*  smask = (int*)(red + 512);

    int qt = blockIdx.x, bh = blockIdx.y;
    int b = bh >> 3, h = bh & 7;
    int tid = threadIdx.x, lane = tid & 31, warp = tid >> 5;
    int mw = warp >> 2, nw = warp & 3;
    int lr = lane >> 2, lc = lane & 3;

    const __nv_bfloat16* Qg = qkv + (size_t)(b * Sc + qt * 128) * NQKV + h * DKc;
    const __nv_bfloat16* Kg = qkv + (size_t)(b * Sc) * NQKV + HDc + h * DKc;
    const __nv_bfloat16* Vg = qkv + (size_t)(b * Sc) * NQKV + 2 * HDc + h * DKc;

    #pragma unroll
    for (int i = 0; i < 8; i++) {
        int ch = tid + i * 512;
        int r = ch >> 5, c = (ch & 31) << 3;
        cpa16(&sQ[r * PQA + c], Qg + (size_t)r * NQKV + c);
    }
    #pragma unroll
    for (int i = 0; i < 16; i++) {
        int ch = tid + i * 512;
        int r = ch >> 5, c = (ch & 31) << 3;
        cpa16(&sK[r * PKA + c], Kg + (size_t)r * NQKV + c);
    }
    if (tid < 256) smask[tid] = attn_m[b * Sc + tid];
    cpa_commit();
    cpa_wait0();
    __syncthreads();

    uint32_t qBase = (uint32_t)__cvta_generic_to_shared(sQ);
    uint32_t kBase = (uint32_t)__cvta_generic_to_shared(sK);

    int aOff[2];
    #pragma unroll
    for (int mi = 0; mi < 2; mi++)
        aOff[mi] = (mw * 32 + mi * 16 + (lane & 15)) * PQA + ((lane >> 4) << 3);
    int bOff1[4];
    #pragma unroll
    for (int p = 0; p < 4; p++)
        bOff1[p] = (nw * 64 + p * 16 + (lane & 7) + (((lane >> 4) & 1) << 3)) * PKA
                   + (((lane >> 3) & 1) << 3);

    float acc[2][8][4];
    #pragma unroll
    for (int mi = 0; mi < 2; mi++)
        #pragma unroll
        for (int ni = 0; ni < 8; ni++)
            #pragma unroll
            for (int k = 0; k < 4; k++) acc[mi][ni][k] = 0.0f;

    #pragma unroll
    for (int kk = 0; kk < 256; kk += 16) {
        uint32_t af[2][4], bf[8][2];
        #pragma unroll
        for (int mi = 0; mi < 2; mi++)
            ldsm4(af[mi][0], af[mi][1], af[mi][2], af[mi][3], qBase + 2 * (aOff[mi] + kk));
        #pragma unroll
        for (int p = 0; p < 4; p++)
            ldsm4(bf[2*p][0], bf[2*p][1], bf[2*p+1][0], bf[2*p+1][1],
                  kBase + 2 * (bOff1[p] + kk));
        #pragma unroll
        for (int mi = 0; mi < 2; mi++)
            #pragma unroll
            for (int ni = 0; ni < 8; ni++)
                MMA_BF16(acc[mi][ni], af[mi][0], af[mi][1], af[mi][2], af[mi][3],
                         bf[ni][0], bf[ni][1]);
    }
    __syncthreads();

    #pragma unroll
    for (int i = 0; i < 16; i++) {
        int ch = tid + i * 512;
        int r = ch >> 5, c = (ch & 31) << 3;
        cpa16(&sK[r * PKA + c], Vg + (size_t)r * NQKV + c);
    }
    cpa_commit();

    #pragma unroll
    for (int ni = 0; ni < 8; ni++) {
        int col = nw * 64 + ni * 8 + lc * 2;
        int mk0 = smask[col], mk1 = smask[col + 1];
        #pragma unroll
        for (int mi = 0; mi < 2; mi++) {
            #pragma unroll
            for (int hh = 0; hh < 2; hh++) {
                float v0 = acc[mi][ni][hh * 2]     * 0.0625f;
                float v1 = acc[mi][ni][hh * 2 + 1] * 0.0625f;
                acc[mi][ni][hh * 2]     = mk0 ? -1e9f : v0;
                acc[mi][ni][hh * 2 + 1] = mk1 ? -1e9f : v1;
            }
        }
    }

    float mx[2][2];
    #pragma unroll
    for (int mi = 0; mi < 2; mi++)
        #pragma unroll
        for (int hh = 0; hh < 2; hh++) {
            float m = -3e38f;
            #pragma unroll
            for (int ni = 0; ni < 8; ni++)
                m = fmaxf(m, fmaxf(acc[mi][ni][hh * 2], acc[mi][ni][hh * 2 + 1]));
            m = fmaxf(m, __shfl_xor_sync(0xFFFFFFFFu, m, 1));
            m = fmaxf(m, __shfl_xor_sync(0xFFFFFFFFu, m, 2));
            mx[mi][hh] = m;
        }
    if (lc == 0) {
        #pragma unroll
        for (int mi = 0; mi < 2; mi++)
            #pragma unroll
            for (int hh = 0; hh < 2; hh++)
                red[nw * 128 + mw * 32 + mi * 16 + hh * 8 + lr] = mx[mi][hh];
    }
    __syncthreads();
    #pragma unroll
    for (int mi = 0; mi < 2; mi++)
        #pragma unroll
        for (int hh = 0; hh < 2; hh++) {
            int row = mw * 32 + mi * 16 + hh * 8 + lr;
            mx[mi][hh] = fmaxf(fmaxf(red[row], red[128 + row]),
                               fmaxf(red[256 + row], red[384 + row]));
        }
    __syncthreads();

    float sums[2][2];
    #pragma unroll
    for (int mi = 0; mi < 2; mi++)
        #pragma unroll
        for (int hh = 0; hh < 2; hh++) {
            float s = 0.0f;
            #pragma unroll
            for (int ni = 0; ni < 8; ni++) {
                float e0 = expf(acc[mi][ni][hh * 2]     - mx[mi][hh]);
                float e1 = expf(acc[mi][ni][hh * 2 + 1] - mx[mi][hh]);
                acc[mi][ni][hh * 2]     = e0;
                acc[mi][ni][hh * 2 + 1] = e1;
                s += e0 + e1;
            }
            s += __shfl_xor_sync(0xFFFFFFFFu, s, 1);
            s += __shfl_xor_sync(0xFFFFFFFFu, s, 2);
            sums[mi][hh] = s;
        }
    if (lc == 0) {
        #pragma unroll
        for (int mi = 0; mi < 2; mi++)
            #pragma unroll
            for (int hh = 0; hh < 2; hh++)
                red[nw * 128 + mw * 32 + mi * 16 + hh * 8 + lr] = sums[mi][hh];
    }
    __syncthreads();
    #pragma unroll
    for (int mi = 0; mi < 2; mi++)
        #pragma unroll
        for (int hh = 0; hh < 2; hh++) {
            int row = mw * 32 + mi * 16 + hh * 8 + lr;
            float tot = red[row] + red[128 + row] + red[256 + row] + red[384 + row];
            sums[mi][hh] = 1.0f / tot;
        }

    #pragma unroll
    for (int mi = 0; mi < 2; mi++)
        #pragma unroll
        for (int hh = 0; hh < 2; hh++) {
            int row = mw * 32 + mi * 16 + hh * 8 + lr;
            float inv = sums[mi][hh];
            #pragma unroll
            for (int ni = 0; ni < 8; ni++) {
                int col = nw * 64 + ni * 8 + lc * 2;
                __nv_bfloat162 pr;
                pr.x = __float2bfloat16_rn(acc[mi][ni][hh * 2]     * inv);
                pr.y = __float2bfloat16_rn(acc[mi][ni][hh * 2 + 1] * inv);
                *(__nv_bfloat162*)(sQ + row * PQA + col) = pr;
            }
        }
    cpa_wait0();
    __syncthreads();

    int bOff2[4];
    #pragma unroll
    for (int p = 0; p < 4; p++)
        bOff2[p] = ((lane & 7) + (((lane >> 3) & 1) << 3)) * PKA
                   + nw * 64 + p * 16 + (((lane >> 4) & 1) << 3);

    #pragma unroll
    for (int mi = 0; mi < 2; mi++)
        #pragma unroll
        for (int ni = 0; ni < 8; ni++)
            #pragma unroll
            for (int k = 0; k < 4; k++) acc[mi][ni][k] = 0.0f;

    #pragma unroll
    for (int kk = 0; kk < 256; kk += 16) {
        uint32_t af[2][4], bf[8][2];
        #pragma unroll
        for (int mi = 0; mi < 2; mi++)
            ldsm4(af[mi][0], af[mi][1], af[mi][2], af[mi][3], qBase + 2 * (aOff[mi] + kk));
        #pragma unroll
        for (int p = 0; p < 4; p++)
            ldsm4t(bf[2*p][0], bf[2*p][1], bf[2*p+1][0], bf[2*p+1][1],
                   kBase + 2 * (bOff2[p] + kk * PKA));
        #pragma unroll
        for (int mi = 0; mi < 2; mi++)
            #pragma unroll
            for (int ni = 0; ni < 8; ni++)
                MMA_BF16(acc[mi][ni], af[mi][0], af[mi][1], af[mi][2], af[mi][3],
                         bf[ni][0], bf[ni][1]);
    }

    #pragma unroll
    for (int mi = 0; mi < 2; mi++)
        #pragma unroll
        for (int ni = 0; ni < 8; ni++) {
            int col = h * DKc + nw * 64 + ni * 8 + lc * 2;
            #pragma unroll
            for (int hh = 0; hh < 2; hh++) {
                int grow = b * Sc + qt * 128 + mw * 32 + mi * 16 + hh * 8 + lr;
                __nv_bfloat162 o2;
                o2.x = __float2bfloat16_rn(acc[mi][ni][hh * 2]);
                o2.y = __float2bfloat16_rn(acc[mi][ni][hh * 2 + 1]);
                *(__nv_bfloat162*)(out + (size_t)grow * HDc + col) = o2;
            }
        }
}

// ---------------- bf16 MMA GEMM: CTA 128x256, warps 64x64, BK=32, 3-stage --------
#define APADh 40
#define BPADh 264          // 256 + 8
#define ASTGh (128*APADh)  // 5120 halves
#define BSTGh (32*BPADh)   // 8448 halves
#define NSTAGE 3
#define SMEM_G2 ((NSTAGE*ASTGh + NSTAGE*BSTGh) * 2)   // 81408 B

__global__ __launch_bounds__(256, 1)
void bgemm_kernel(const __nv_bfloat16* __restrict__ A, int lda, long long sA,
                  const __nv_bfloat16* __restrict__ Bp, int ldb, long long sB,
                  void* __restrict__ Cv, int ldc, long long sC,
                  int K, const float* __restrict__ bias,
                  int relu, int outbf)
{
    int z = blockIdx.z;
    A  += (size_t)z * sA;
    Bp += (size_t)z * sB;
    size_t coff = (size_t)z * sC;

    extern __shared__ __nv_bfloat16 sm[];
    __nv_bfloat16* As = sm;
    __nv_bfloat16* Bs = sm + NSTAGE * ASTGh;

    int tid = threadIdx.x;
    int lane = tid & 31, warp = tid >> 5;
    int mBase = (warp >> 2) * 64;
    int nBase = (warp & 3) * 64;
    int lr = lane >> 2, lc = lane & 3;

    const __nv_bfloat16* Ag = A + (size_t)(blockIdx.y * 128) * lda;
    const __nv_bfloat16* Bg = Bp + blockIdx.x * 256;

    float acc[4][8][4];
    #pragma unroll
    for (int i = 0; i < 4; i++)
        #pragma unroll
        for (int j = 0; j < 8; j++)
            #pragma unroll
            for (int k = 0; k < 4; k++) acc[i][j][k] = 0.0f;

    auto load_stage = [&](int st, int kt) {
        int k0 = kt * 32;
        // A: 128 x 32 halves = 512 chunks of 16B
        #pragma unroll
        for (int i = 0; i < 2; i++) {
            int ch = tid + (i << 8);
            int r = ch >> 2, c = (ch & 3) << 3;
            cpa16(&As[st * ASTGh + r * APADh + c], Ag + (size_t)r * lda + k0 + c);
        }
        // B: 32 x 256 halves = 1024 chunks
        #pragma unroll
        for (int i = 0; i < 4; i++) {
            int ch = tid + (i << 8);
            int r = ch >> 5, c = (ch & 31) << 3;
            cpa16(&Bs[st * BSTGh + r * BPADh + c], Bg + (size_t)(k0 + r) * ldb + c);
        }
    };

    uint32_t aBase = (uint32_t)__cvta_generic_to_shared(As);
    uint32_t bBase = (uint32_t)__cvta_generic_to_shared(Bs);
    int aRow[4];
    #pragma unroll
    for (int mt = 0; mt < 4; mt++)
        aRow[mt] = (mBase + mt * 16 + (lane & 15)) * APADh + ((lane >> 4) << 3);
    int bRow[4];
    #pragma unroll
    for (int p = 0; p < 4; p++)
        bRow[p] = ((lane & 7) + (((lane >> 3) & 1) << 3)) * BPADh
                  + nBase + p * 16 + (((lane >> 4) & 1) << 3);

    int kTiles = K >> 5;
    load_stage(0, 0);
    cpa_commit();
    if (kTiles > 1) load_stage(1, 1);
    cpa_commit();
    if (kTiles > 2) load_stage(2, 2);
    cpa_commit();

    int st = 0;
    for (int kt = 0; kt < kTiles; kt++) {
        cpa_wait2();
        __syncthreads();
        uint32_t aS = aBase + st * (ASTGh * 2);
        uint32_t bS = bBase + st * (BSTGh * 2);

        #pragma unroll
        for (int kk = 0; kk < 32; kk += 16) {
            uint32_t af[4][4], bf[8][2];
            #pragma unroll
            for (int mt = 0; mt < 4; mt++)
                ldsm4(af[mt][0], af[mt][1], af[mt][2], af[mt][3],
                      aS + 2 * (aRow[mt] + kk));
            #pragma unroll
            for (int p = 0; p < 4; p++)
                ldsm4t(bf[2*p][0], bf[2*p][1], bf[2*p+1][0], bf[2*p+1][1],
                       bS + 2 * (bRow[p] + kk * BPADh));
            #pragma unroll
            for (int mt = 0; mt < 4; mt++)
                #pragma unroll
                for (int nt = 0; nt < 8; nt++)
                    MMA_BF16(acc[mt][nt], af[mt][0], af[mt][1], af[mt][2], af[mt][3],
                             bf[nt][0], bf[nt][1]);
        }
        __syncthreads();
        if (kt + 3 < kTiles) load_stage(st, kt + 3);
        cpa_commit();
        st = (st == NSTAGE - 1) ? 0 : st + 1;
    }

    float* Cf = (float*)Cv + coff;
    __nv_bfloat16* Cb = (__nv_bfloat16*)Cv + coff;
    #pragma unroll
    for (int mt = 0; mt < 4; mt++) {
        #pragma unroll
        for (int nt = 0; nt < 8; nt++) {
            int row0 = blockIdx.y * 128 + mBase + mt * 16 + lr;
            int col  = blockIdx.x * 256 + nBase + nt * 8 + lc * 2;
            float b0 = bias ? bias[col]     : 0.0f;
            float b1 = bias ? bias[col + 1] : 0.0f;
            #pragma unroll
            for (int hh = 0; hh < 2; hh++) {
                int row = row0 + hh * 8;
                float c0 = acc[mt][nt][hh * 2 + 0] + b0;
                float c1 = acc[mt][nt][hh * 2 + 1] + b1;
                if (relu) { c0 = fmaxf(c0, 0.0f); c1 = fmaxf(c1, 0.0f); }
                size_t off = (size_t)row * ldc + col;
                if (outbf) {
                    __nv_bfloat162 h2;
                    h2.x = __float2bfloat16_rn(c0);
                    h2.y = __float2bfloat16_rn(c1);
                    *(__nv_bfloat162*)(Cb + off) = h2;
                } else {
                    *(float2*)(Cf + off) = make_float2(c0, c1);
                }
            }
        }
    }
}

static void bgemm(const __nv_bfloat16* A, int lda, long long sA,
                  const __nv_bfloat16* B, int ldb, long long sB,
                  void* C, int ldc, long long sC,
                  int M, int N, int K, int nz,
                  const float* bias, int relu, int outbf)
{
    dim3 grid(N / 256, M / 128, nz), block(256);
    bgemm_kernel<<<grid, block, SMEM_G2>>>(A, lda, sA, B, ldb, sB,
                                           C, ldc, sC, K, bias, relu, outbf);
}

extern "C" void kernel_launch(void* const* d_in, const int* in_sizes, int n_in,
                              void* d_out, int out_size)
{
    const float* data    = (const float*)d_in[0];
    const int*   attn_m  = (const int*)  d_in[1];
    const int*   view_ix = (const int*)  d_in[2];
    const float* seg     = (const float*)d_in[3];
    const float* Wq = (const float*)d_in[4];
    const float* bq = (const float*)d_in[5];
    const float* Wk = (const float*)d_in[6];
    const float* bk = (const float*)d_in[7];
    const float* Wv = (const float*)d_in[8];
    const float* bv = (const float*)d_in[9];
    const float* Wo = (const float*)d_in[10];
    const float* bo = (const float*)d_in[11];
    const float* W1 = (const float*)d_in[12];
    const float* b1 = (const float*)d_in[13];
    const float* W2 = (const float*)d_in[14];
    const float* b2 = (const float*)d_in[15];
    const float* alpha1 = (const float*)d_in[16];
    const float* bias1  = (const float*)d_in[17];
    const float* alpha2 = (const float*)d_in[18];
    const float* bias2  = (const float*)d_in[19];
    const float* alphaf = (const float*)d_in[20];
    const float* biasf  = (const float*)d_in[21];
    float* out = (float*)d_out;

    static float *px = nullptr, *ppart, *pbqkv;
    static __nv_bfloat16 *px2b, *pqkv, *pob, *pfb;
    static __nv_bfloat16 *wqkv, *wo, *w1, *w2;
    if (!px) {
        cudaGetSymbolAddress((void**)&px,    g_x);
        cudaGetSymbolAddress((void**)&ppart, g_part);
        cudaGetSymbolAddress((void**)&pbqkv, g_bqkv);
        cudaGetSymbolAddress((void**)&px2b,  g_x2b);
        cudaGetSymbolAddress((void**)&pqkv,  g_qkvb);
        cudaGetSymbolAddress((void**)&pob,   g_ob);
        cudaGetSymbolAddress((void**)&pfb,   g_fb);
        cudaGetSymbolAddress((void**)&wqkv,  g_wqkv);
        cudaGetSymbolAddress((void**)&wo,    g_wo);
        cudaGetSymbolAddress((void**)&w1,    g_w1);
        cudaGetSymbolAddress((void**)&w2,    g_w2);
        cudaFuncSetAttribute(bgemm_kernel,
                             cudaFuncAttributeMaxDynamicSharedMemorySize, SMEM_G2);
        cudaFuncSetAttribute(attn_kernel,
                             cudaFuncAttributeMaxDynamicSharedMemorySize, ATT_SMEM);
    }

    {
        int t4 = Lc * Dc * NQKV / 4;
        f2b_qkv_kernel<<<(t4 + 255) / 256, 256>>>(Wq, Wk, Wv, wqkv);
        int n4 = Lc * WSZ / 4;
        f2b_multi_kernel<<<(3 * n4 + 255) / 256, 256>>>(Wo, wo, W1, w1, W2, w2, n4);
        bias_qkv_kernel<<<(Lc * NQKV + 255) / 256, 256>>>(bq, bk, bv, pbqkv);
    }

    embed_ln_kernel<<<Bc * Sc, 128>>>(data, seg, view_ix, alpha1, bias1, px, px2b);

    for (int i = 0; i < Lc; i++) {
        // fused QKV: [2048,512] @ [512,6144] -> bf16
        bgemm(px2b, Dc, 0, wqkv + (long long)i * Dc * NQKV, NQKV, 0,
              pqkv, NQKV, 0, Bc * Sc, NQKV, Dc, 1,
              pbqkv + i * NQKV, 0, 1);

        // fused attention
        {
            dim3 grid(2, Bc * Hc), block(512);
            attn_kernel<<<grid, block, ATT_SMEM>>>(pqkv, attn_m, pob);
        }

        // Wo: split-K=4 -> fp32 partials
        bgemm(pob, HDc, 512,
              wo + (long long)i * WSZ, Dc, (long long)512 * Dc,
              ppart, Dc, BSD,
              Bc * Sc, Dc, 512, 4,
              nullptr, 0, 0);
        reduce_ln_kernel<<<Bc * Sc, 128>>>(ppart, bo + i * Dc, px,
                                           alpha2 + i * Dc, bias2 + i * Dc,
                                           px2b, nullptr);

        // ff = relu(x2 @ W1 + b1) -> bf16
        bgemm(px2b, Dc, 0, w1 + (long long)i * WSZ, DFFc, 0,
              pfb, DFFc, 0, Bc * Sc, DFFc, Dc, 1,
              b1 + i * DFFc, 1, 1);

        // W2: split-K=4 -> fp32 partials
        bgemm(pfb, DFFc, 512,
              w2 + (long long)i * WSZ, Dc, (long long)512 * Dc,
              ppart, Dc, BSD,
              Bc * Sc, Dc, 512, 4,
              nullptr, 0, 0);

        if (i < Lc - 1)
            reduce_ln_kernel<<<Bc * Sc, 128>>>(ppart, b2 + i * Dc, px,
                                               alpha1 + (i + 1) * Dc, bias1 + (i + 1) * Dc,
                                               px2b, nullptr);
        else
            reduce_ln_kernel<<<Bc * Sc, 128>>>(ppart, b2 + i * Dc, px,
                                               alphaf, biasf,
                                               nullptr, out);
    }
}